// round 2
// baseline (speedup 1.0000x reference)
#include <cuda_runtime.h>
#include <cstdint>
#include <cstddef>

// ---------------- problem constants ----------------
#define T_    4
#define B_    8
#define NSEQ  1024
#define C_    768
#define HD_   3072
#define H_    8
#define D_    96
#define W_    8
#define NW_   (NSEQ / W_)           // 128
#define BN_TOK (B_ * NSEQ)          // 8192
#define M_TOT (T_ * BN_TOK)         // 32768
#define PLANE_C ((size_t)BN_TOK * C_)   // 6291456
#define PLANE_H ((size_t)BN_TOK * HD_)  // 25165824

// ---------------- device scratch (no allocs allowed) ----------------
__device__ float g_buf1[(size_t)M_TOT * HD_];      // pre-activations (max width Hd); h-spikes in place
__device__ float g_spk [(size_t)M_TOT * C_ * 3];   // q,k,v spikes
__device__ float g_obuf[(size_t)M_TOT * C_];       // attention out / f2 pre
__device__ float g_x1  [(size_t)M_TOT * C_];       // residual after proj

// ---------------- fused GEMM + BN affine ----------------
// Y[m,n] = (sum_k A[m,k]*W[n,k] + bias[n]) * scale[n] + shift[n]
// M = M_TOT (divisible by 128); N divisible by 128; K divisible by 16.
__global__ __launch_bounds__(256, 2)
void gemm_bn(const float* __restrict__ A, const float* __restrict__ Wt,
             const float* __restrict__ bia, const float* __restrict__ sca,
             const float* __restrict__ shf, float* __restrict__ Y,
             int N, int K)
{
    __shared__ float As[16][128];
    __shared__ float Bs[16][128];

    const int bm = blockIdx.y * 128;
    const int bn = blockIdx.x * 128;
    const int tid = threadIdx.x;
    const int tr = tid >> 4;   // 0..15
    const int tc = tid & 15;   // 0..15

    float acc[8][8];
    #pragma unroll
    for (int i = 0; i < 8; i++)
        #pragma unroll
        for (int j = 0; j < 8; j++) acc[i][j] = 0.f;

    const float* Aptr = A + (size_t)bm * K;
    const float* Wptr = Wt + (size_t)bn * K;

    for (int k0 = 0; k0 < K; k0 += 16) {
        #pragma unroll
        for (int u = 0; u < 2; u++) {
            int L   = tid + 256 * u;     // 0..511
            int row = L >> 2;            // 0..127
            int f4  = (L & 3) << 2;      // 0,4,8,12
            float4 va = *(const float4*)(Aptr + (size_t)row * K + k0 + f4);
            As[f4 + 0][row] = va.x; As[f4 + 1][row] = va.y;
            As[f4 + 2][row] = va.z; As[f4 + 3][row] = va.w;
            float4 vb = *(const float4*)(Wptr + (size_t)row * K + k0 + f4);
            Bs[f4 + 0][row] = vb.x; Bs[f4 + 1][row] = vb.y;
            Bs[f4 + 2][row] = vb.z; Bs[f4 + 3][row] = vb.w;
        }
        __syncthreads();
        #pragma unroll
        for (int kk = 0; kk < 16; kk++) {
            float a[8], b[8];
            *(float4*)&a[0] = *(const float4*)&As[kk][tr * 8];
            *(float4*)&a[4] = *(const float4*)&As[kk][tr * 8 + 4];
            *(float4*)&b[0] = *(const float4*)&Bs[kk][tc * 8];
            *(float4*)&b[4] = *(const float4*)&Bs[kk][tc * 8 + 4];
            #pragma unroll
            for (int i = 0; i < 8; i++)
                #pragma unroll
                for (int j = 0; j < 8; j++)
                    acc[i][j] += a[i] * b[j];
        }
        __syncthreads();
    }

    float sc[8], bb[8], sh[8];
    #pragma unroll
    for (int j = 0; j < 8; j++) {
        int col = bn + tc * 8 + j;
        sc[j] = sca[col]; bb[j] = bia[col]; sh[j] = shf[col];
    }
    #pragma unroll
    for (int i = 0; i < 8; i++) {
        int row = bm + tr * 8 + i;
        float* Yr = Y + (size_t)row * N + bn + tc * 8;
        #pragma unroll
        for (int j = 0; j < 8; j++)
            Yr[j] = (acc[i][j] + bb[j]) * sc[j] + sh[j];
    }
}

// ---------------- LIF over T (tau=2, hard reset) ----------------
// v = v + (x - v)/2; s = (v >= vth); v = s ? 0 : v
// Safe in-place (spk == pre): each thread reads pre[t][idx] before writing spk[t][idx].
__global__ void lif_kernel(const float4* __restrict__ pre, float4* __restrict__ spk,
                           size_t plane4, float vth)
{
    size_t idx = (size_t)blockIdx.x * blockDim.x + threadIdx.x;
    if (idx >= plane4) return;
    float vx = 0.f, vy = 0.f, vz = 0.f, vw = 0.f;
    #pragma unroll
    for (int t = 0; t < T_; t++) {
        float4 xv = pre[(size_t)t * plane4 + idx];
        float4 s;
        vx = vx + (xv.x - vx) * 0.5f; s.x = (vx >= vth) ? 1.f : 0.f; if (s.x != 0.f) vx = 0.f;
        vy = vy + (xv.y - vy) * 0.5f; s.y = (vy >= vth) ? 1.f : 0.f; if (s.y != 0.f) vy = 0.f;
        vz = vz + (xv.z - vz) * 0.5f; s.z = (vz >= vth) ? 1.f : 0.f; if (s.z != 0.f) vz = 0.f;
        vw = vw + (xv.w - vw) * 0.5f; s.w = (vw >= vth) ? 1.f : 0.f; if (s.w != 0.f) vw = 0.f;
        spk[(size_t)t * plane4 + idx] = s;
    }
}

// same, but out[t] = res[t] + spike (residual fusion)
__global__ void lif_add_kernel(const float4* __restrict__ pre, const float4* __restrict__ res,
                               float4* __restrict__ out, size_t plane4, float vth)
{
    size_t idx = (size_t)blockIdx.x * blockDim.x + threadIdx.x;
    if (idx >= plane4) return;
    float vx = 0.f, vy = 0.f, vz = 0.f, vw = 0.f;
    #pragma unroll
    for (int t = 0; t < T_; t++) {
        float4 xv = pre[(size_t)t * plane4 + idx];
        float4 rv = res[(size_t)t * plane4 + idx];
        float4 o;
        vx = vx + (xv.x - vx) * 0.5f; o.x = rv.x + ((vx >= vth) ? 1.f : 0.f); if (vx >= vth) vx = 0.f;
        vy = vy + (xv.y - vy) * 0.5f; o.y = rv.y + ((vy >= vth) ? 1.f : 0.f); if (vy >= vth) vy = 0.f;
        vz = vz + (xv.z - vz) * 0.5f; o.z = rv.z + ((vz >= vth) ? 1.f : 0.f); if (vz >= vth) vz = 0.f;
        vw = vw + (xv.w - vw) * 0.5f; o.w = rv.w + ((vw >= vth) ? 1.f : 0.f); if (vw >= vth) vw = 0.f;
        out[(size_t)t * plane4 + idx] = o;
    }
}

// ---------------- local windowed attention ----------------
// grid (NW_, B_, T_), 128 threads. Loops all H_ heads.
// q,k,v spike tensors laid out (T,B,N,C) with c = h*D + d.
// window w=8, look_backward=1 -> 16 keys; first window's lookback masked.
__global__ void attn_kernel(const float* __restrict__ qg, const float* __restrict__ kg,
                            const float* __restrict__ vg, float* __restrict__ og)
{
    __shared__ float Qs[8][97];
    __shared__ float Ks[16][97];
    __shared__ float Vs[16][97];
    __shared__ float At[8][16];

    const int nwi = blockIdx.x;
    const int b   = blockIdx.y;
    const int t   = blockIdx.z;
    const int tid = threadIdx.x;
    const size_t base = ((size_t)t * B_ + b) * (size_t)NSEQ * C_;
    const int n0 = nwi * W_;
    const float scale = 0.10206207261596577f; // 96^-0.5

    for (int h = 0; h < H_; h++) {
        const int c0 = h * D_;
        for (int r = tid; r < 8 * 96; r += 128) {
            int i = r / 96, d = r - i * 96;
            Qs[i][d] = qg[base + (size_t)(n0 + i) * C_ + c0 + d];
        }
        for (int r = tid; r < 16 * 96; r += 128) {
            int j = r / 96, d = r - j * 96;
            int n = n0 - 8 + j;
            float kv = 0.f, vv = 0.f;
            if (n >= 0) {
                size_t off = base + (size_t)n * C_ + c0 + d;
                kv = kg[off]; vv = vg[off];
            }
            Ks[j][d] = kv; Vs[j][d] = vv;
        }
        __syncthreads();

        const int i = tid >> 4, j = tid & 15;
        float acc = 0.f;
        #pragma unroll
        for (int d = 0; d < 96; d++) acc += Qs[i][d] * Ks[j][d];
        float sim = acc * scale;
        if (nwi == 0 && j < 8) sim = -3.0e38f;

        float mx = sim;
        #pragma unroll
        for (int off = 8; off > 0; off >>= 1)
            mx = fmaxf(mx, __shfl_xor_sync(0xffffffffu, mx, off));
        float e = expf(sim - mx);
        float ssum = e;
        #pragma unroll
        for (int off = 8; off > 0; off >>= 1)
            ssum += __shfl_xor_sync(0xffffffffu, ssum, off);
        At[i][j] = e / ssum;
        __syncthreads();

        for (int r = tid; r < 8 * 96; r += 128) {
            int ii = r / 96, d = r - ii * 96;
            float o = 0.f;
            #pragma unroll
            for (int jj = 0; jj < 16; jj++) o += At[ii][jj] * Vs[jj][d];
            og[base + (size_t)(n0 + ii) * C_ + c0 + d] = o;
        }
        __syncthreads();
    }
}

// ---------------- launch ----------------
extern "C" void kernel_launch(void* const* d_in, const int* in_sizes, int n_in,
                              void* d_out, int out_size)
{
    const float* x   = (const float*)d_in[0];
    const float* qw  = (const float*)d_in[1];
    const float* qb  = (const float*)d_in[2];
    const float* qs  = (const float*)d_in[3];
    const float* qt  = (const float*)d_in[4];
    const float* kw  = (const float*)d_in[5];
    const float* kb  = (const float*)d_in[6];
    const float* ks  = (const float*)d_in[7];
    const float* kt  = (const float*)d_in[8];
    const float* vw  = (const float*)d_in[9];
    const float* vb  = (const float*)d_in[10];
    const float* vs  = (const float*)d_in[11];
    const float* vt  = (const float*)d_in[12];
    const float* pw  = (const float*)d_in[13];
    const float* pb  = (const float*)d_in[14];
    const float* ps  = (const float*)d_in[15];
    const float* pt  = (const float*)d_in[16];
    const float* f1w = (const float*)d_in[17];
    const float* f1b = (const float*)d_in[18];
    const float* f1s = (const float*)d_in[19];
    const float* f1t = (const float*)d_in[20];
    const float* f2w = (const float*)d_in[21];
    const float* f2b = (const float*)d_in[22];
    const float* f2s = (const float*)d_in[23];
    const float* f2t = (const float*)d_in[24];

    float *buf1, *spk, *obuf, *x1b;
    cudaGetSymbolAddress((void**)&buf1, g_buf1);
    cudaGetSymbolAddress((void**)&spk,  g_spk);
    cudaGetSymbolAddress((void**)&obuf, g_obuf);
    cudaGetSymbolAddress((void**)&x1b,  g_x1);

    const size_t MC = (size_t)M_TOT * C_;
    const dim3 blk(256);
    const dim3 g768(C_ / 128, M_TOT / 128);    // (6, 256)
    const dim3 g3072(HD_ / 128, M_TOT / 128);  // (24, 256)
    const int lifBlocksC = (int)((PLANE_C / 4 + 255) / 256);
    const int lifBlocksH = (int)((PLANE_H / 4 + 255) / 256);

    // q,k,v: GEMM + BN, then LIF -> spikes
    const float* Ws[3] = {qw, kw, vw};
    const float* Bs[3] = {qb, kb, vb};
    const float* Ss[3] = {qs, ks, vs};
    const float* Ts[3] = {qt, kt, vt};
    for (int l = 0; l < 3; l++)
        gemm_bn<<<g768, blk>>>(x, Ws[l], Bs[l], Ss[l], Ts[l], buf1 + (size_t)l * MC, C_, C_);
    for (int l = 0; l < 3; l++)
        lif_kernel<<<lifBlocksC, 256>>>((const float4*)(buf1 + (size_t)l * MC),
                                        (float4*)(spk + (size_t)l * MC), PLANE_C / 4, 1.0f);

    // local attention on spikes
    attn_kernel<<<dim3(NW_, B_, T_), 128>>>(spk, spk + MC, spk + 2 * MC, obuf);

    // attn_lif (vth=0.5), in-place
    lif_kernel<<<lifBlocksC, 256>>>((const float4*)obuf, (float4*)obuf, PLANE_C / 4, 0.5f);

    // proj GEMM + BN, LIF with residual: x1 = x + spikes
    gemm_bn<<<g768, blk>>>(obuf, pw, pb, ps, pt, buf1, C_, C_);
    lif_add_kernel<<<lifBlocksC, 256>>>((const float4*)buf1, (const float4*)x,
                                        (float4*)x1b, PLANE_C / 4, 1.0f);

    // f1 GEMM + BN, LIF -> h spikes (in place in buf1)
    gemm_bn<<<g3072, blk>>>(x1b, f1w, f1b, f1s, f1t, buf1, HD_, C_);
    lif_kernel<<<lifBlocksH, 256>>>((const float4*)buf1, (float4*)buf1, PLANE_H / 4, 1.0f);

    // f2 GEMM + BN, LIF with residual: out = x1 + spikes
    gemm_bn<<<g768, blk>>>(buf1, f2w, f2b, f2s, f2t, obuf, C_, HD_);
    lif_add_kernel<<<lifBlocksC, 256>>>((const float4*)obuf, (const float4*)x1b,
                                        (float4*)d_out, PLANE_C / 4, 1.0f);
}